// round 5
// baseline (speedup 1.0000x reference)
#include <cuda_runtime.h>
#include <cuda_bf16.h>
#include <cstdint>

#define NPIX 262144               // 512*512 = 2^18
#define HALFCNT 4194304u          // 2^22 threefry counter half
#define GBLK 512                  // k_gramA blocks (512 px each)

// ---------------- device scratch (allocation-free) ----------------
__device__ float g_xt[4 * 210];
__device__ float g_acoef[4 * 8 * 2 * 6];  // [b][r][j][bb0,bb1,p,q,u,v] = 384 floats
__device__ float g_wr[4 * 8];             // softmaxed rank weights (first 8 of 9)
__device__ float g_part[4 * GBLK * 44];   // gram partials per (b, block)
__device__ float g_Cc[4 * 8];             // combine coefs
__device__ float g_Ff[4 * 8];             // noise std coefs
__device__ float g_Kk[4];                 // mean shift

// ---------------- K0a: xt = x @ ctx_w^T + ctx_b ----------------
__global__ void k_xt(const float* __restrict__ x, const float* __restrict__ cw,
                     const float* __restrict__ cb) {
  int f = blockIdx.x;          // 0..209
  int t = threadIdx.x;         // 128
  const float* wrow = cw + f * 512;
  float a0 = 0.f, a1 = 0.f, a2 = 0.f, a3 = 0.f;
  for (int i = t; i < 512; i += 128) {
    float w = wrow[i];
    a0 = fmaf(w, x[i], a0);
    a1 = fmaf(w, x[512 + i], a1);
    a2 = fmaf(w, x[1024 + i], a2);
    a3 = fmaf(w, x[1536 + i], a3);
  }
#pragma unroll
  for (int o = 16; o; o >>= 1) {
    a0 += __shfl_xor_sync(~0u, a0, o);
    a1 += __shfl_xor_sync(~0u, a1, o);
    a2 += __shfl_xor_sync(~0u, a2, o);
    a3 += __shfl_xor_sync(~0u, a3, o);
  }
  __shared__ float sm[4][4];
  int wq = t >> 5, l = t & 31;
  if (l == 0) { sm[wq][0] = a0; sm[wq][1] = a1; sm[wq][2] = a2; sm[wq][3] = a3; }
  __syncthreads();
  if (t == 0) {
    float bb = cb[f];
#pragma unroll
    for (int b = 0; b < 4; b++)
      g_xt[b * 210 + f] = sm[0][b] + sm[1][b] + sm[2][b] + sm[3][b] + bb;
  }
}

// ---------------- K0b: gate, affine modulation coefs, wr softmax ----------------
__global__ void k_mods() {
  int t = threadIdx.x;  // 128
  __shared__ float gated[4][105];
  for (int i = t; i < 420; i += 128) {
    int b = i / 105, k = i - 105 * b;
    float a1 = g_xt[b * 210 + k], a2 = g_xt[b * 210 + 105 + k];
    gated[b][k] = a1 * tanhf(a2);
  }
  __syncthreads();
  if (t < 64) {
    int b = t >> 4, r = (t >> 1) & 7, j = t & 1;
    int base = r * 12 + j * 2;
    float c0 = gated[b][base + 0] + 0.5f;
    float c1 = gated[b][base + 1];
    float bb0 = gated[b][base + 4];
    float bb1 = gated[b][base + 5];
    float s0 = gated[b][base + 8] + 1.0f;
    float s1 = gated[b][base + 9];
    float omc = 1.0f - c0;
    float p = s0 * omc + s1 * c1;
    float q = s0 * c1 - s1 * omc;
    float u = s0 * c0 - s1 * c1;
    float v = -(s0 * c1 + s1 * c0);
    float* dst = &g_acoef[((b * 8 + r) * 2 + j) * 6];
    dst[0] = bb0; dst[1] = bb1; dst[2] = p; dst[3] = q; dst[4] = u; dst[5] = v;
  }
  if (t < 4) {
    int b = t;
    float w[9];
#pragma unroll
    for (int i = 0; i < 9; i++) w[i] = gated[b][96 + i];
    w[8] += 0.35355339059327373f;  // 1/sqrt(8)
    float ss = 0.f;
#pragma unroll
    for (int i = 0; i < 9; i++) ss += w[i] * w[i];
    float inv = 1.0f / fmaxf(sqrtf(ss), 1e-12f);
    float mx = -3.4e38f;
#pragma unroll
    for (int i = 0; i < 9; i++) { w[i] *= inv; mx = fmaxf(mx, w[i]); }
    float sum = 0.f;
#pragma unroll
    for (int i = 0; i < 9; i++) { w[i] = expf(w[i] - mx); sum += w[i]; }
    float isum = 1.0f / sum;
#pragma unroll
    for (int i = 0; i < 8; i++) g_wr[b * 8 + i] = w[i] * isum;
  }
}

// w for one (b,r,pixel) given the 12 affine coefs and the 2 complex weights
__device__ __forceinline__ float wval(const float* c, float are, float aim,
                                      float bre, float bim,
                                      float a1re, float a1im, float b1re, float b1im) {
  float nr = c[0] + c[2] * are + c[3] * aim + c[4] * bre + c[5] * bim;
  float ni = c[1] - c[3] * are + c[2] * aim - c[5] * bre + c[4] * bim;
  float er = c[6] + c[8] * a1re + c[9] * a1im + c[10] * b1re + c[11] * b1im;
  float ei = c[7] - c[9] * a1re + c[8] * a1im - c[11] * b1re + c[10] * b1im;
  float d2 = er * er + ei * ei;
  float inv = rsqrtf(fmaxf(d2, 1e-12f));
  return (nr * er + ni * ei) * inv;
}

// triangular pair index: s <= t
#define TIDX(s, t) ((s) * 8 - (s) * ((s)-1) / 2 + ((t) - (s)))

// ---------------- K1: fused w-compute + Gram (no DRAM scratch) ----------------
// grid = GBLK blocks x 256 threads; block covers 512 pixels.
// dynamic smem: sw[32*512] (w values) + scf[384] (coefs) = 67072 B
__global__ void __launch_bounds__(256) k_gramA(const float* __restrict__ wt) {
  extern __shared__ float dyn[];
  float* sw = dyn;                 // [(b*8+r)*512 + px]
  float* scf = dyn + 32 * 512;     // 384 coefs
  __shared__ float red[8][44];
  int t = threadIdx.x;
  for (int i = t; i < 384; i += 256) scf[i] = g_acoef[i];
  __syncthreads();
  // ---- phase 1: compute w for 2 pixels (float4 = 2 complex) ----
  int q = blockIdx.x * 256 + t;             // float4 index within plane
  const float4* W4 = (const float4*)wt;
#pragma unroll
  for (int r = 0; r < 8; r++) {
    float4 A0 = W4[(size_t)(4 * r + 0) * (NPIX / 2) + q];
    float4 A1 = W4[(size_t)(4 * r + 1) * (NPIX / 2) + q];
    float4 B0 = W4[(size_t)(4 * r + 2) * (NPIX / 2) + q];
    float4 B1 = W4[(size_t)(4 * r + 3) * (NPIX / 2) + q];
#pragma unroll
    for (int b = 0; b < 4; b++) {
      const float* c = &scf[(b * 8 + r) * 12];
      float w0 = wval(c, A0.x, A0.y, B0.x, B0.y, A1.x, A1.y, B1.x, B1.y);
      float w1 = wval(c, A0.z, A0.w, B0.z, B0.w, A1.z, A1.w, B1.z, B1.w);
      ((float2*)sw)[(b * 8 + r) * 256 + t] = make_float2(w0, w1);
    }
  }
  __syncthreads();
  // ---- phase 2: per-batch Gram + sums from smem ----
  int wq = t >> 5, lane = t & 31;
  int b = wq >> 1, half = wq & 1;
  float a[36], su[8];
#pragma unroll
  for (int k = 0; k < 36; k++) a[k] = 0.f;
#pragma unroll
  for (int k = 0; k < 8; k++) su[k] = 0.f;
#pragma unroll
  for (int k = 0; k < 8; k++) {
    int px = half * 256 + k * 32 + lane;
    float v[8];
#pragma unroll
    for (int s = 0; s < 8; s++) v[s] = sw[(b * 8 + s) * 512 + px];
#pragma unroll
    for (int s = 0; s < 8; s++) {
      su[s] += v[s];
#pragma unroll
      for (int u = s; u < 8; u++) a[TIDX(s, u)] = fmaf(v[s], v[u], a[TIDX(s, u)]);
    }
  }
#pragma unroll
  for (int k = 0; k < 36; k++)
#pragma unroll
    for (int o = 16; o; o >>= 1) a[k] += __shfl_xor_sync(~0u, a[k], o);
#pragma unroll
  for (int k = 0; k < 8; k++)
#pragma unroll
    for (int o = 16; o; o >>= 1) su[k] += __shfl_xor_sync(~0u, su[k], o);
  if (lane == 0) {
#pragma unroll
    for (int k = 0; k < 36; k++) red[wq][k] = a[k];
#pragma unroll
    for (int k = 0; k < 8; k++) red[wq][36 + k] = su[k];
  }
  __syncthreads();
  if (t < 176) {
    int bb = t / 44, j = t - 44 * bb;
    g_part[(bb * GBLK + blockIdx.x) * 44 + j] = red[2 * bb][j] + red[2 * bb + 1][j];
  }
}

// ---------------- K3: finalize coefficients ----------------
__global__ void __launch_bounds__(704) k_fin() {
  __shared__ float ph[176][4];
  __shared__ float sG[176];
  int t = threadIdx.x;
  {
    int pair = t >> 2, lane = t & 3;
    int b = pair / 44, j = pair % 44;
    float acc = 0.f;
    for (int blk = lane; blk < GBLK; blk += 4)
      acc += g_part[(b * GBLK + blk) * 44 + j];
    ph[pair][lane] = acc;
  }
  __syncthreads();
  if (t < 176) sG[t] = ph[t][0] + ph[t][1] + ph[t][2] + ph[t][3];
  __syncthreads();
  if (t < 4) {
    int b = t;
    float G[8][8], S[8];
#pragma unroll
    for (int s = 0; s < 8; s++)
#pragma unroll
      for (int u = s; u < 8; u++) { float g = sG[b * 44 + TIDX(s, u)]; G[s][u] = g; G[u][s] = g; }
#pragma unroll
    for (int s = 0; s < 8; s++) S[s] = sG[b * 44 + 36 + s];
    float nc[8];
#pragma unroll
    for (int s = 0; s < 8; s++) nc[s] = fmaxf(sqrtf(G[s][s]), 1e-12f);
    float Gh[8][8];
#pragma unroll
    for (int s = 0; s < 8; s++)
#pragma unroll
      for (int u = 0; u < 8; u++) Gh[s][u] = G[s][u] / (nc[s] * nc[u]);
    const float alpha = 0.1f / (7.0f * 2.8284271247461903f);  // 0.1/(7*sqrt(8))
    float A[8][8];
#pragma unroll
    for (int s = 0; s < 8; s++)
#pragma unroll
      for (int u = 0; u < 8; u++) A[s][u] = (s == u) ? 1.0f : -alpha * Gh[s][u];
    float C[8], K = 0.f;
#pragma unroll
    for (int s = 0; s < 8; s++) C[s] = 0.f;
#pragma unroll
    for (int r = 0; r < 8; r++) {
      float q = 0.f;
#pragma unroll
      for (int u = 0; u < 8; u++) {
        float v = 0.f;
#pragma unroll
        for (int s = 0; s < 8; s++) v += A[r][s] * Gh[s][u];
        q += v * A[r][u];
      }
      float mc = fmaxf(sqrtf(fmaxf(q, 0.f)), 1e-12f);
      double meand = 0.0;
      float wr = g_wr[b * 8 + r];
#pragma unroll
      for (int s = 0; s < 8; s++) {
        float D = A[r][s] / (nc[s] * mc);
        C[s] += wr * D;
        meand += (double)D * (double)S[s];
      }
      meand /= (double)NPIX;
      double var = (1.0 - (double)NPIX * meand * meand) / (double)(NPIX - 1);
      if (var < 0.0) var = 0.0;
      double stdd = sqrt(var);
      if (stdd < 1e-12) stdd = 1e-12;
      g_Ff[b * 8 + r] = 0.01f * wr * (float)stdd;
      K += 0.01f * wr * (float)meand;
    }
#pragma unroll
    for (int s = 0; s < 8; s++) g_Cc[b * 8 + s] = C[s];
    g_Kk[b] = K;
  }
}

// ---------------- threefry2x32 (JAX, key = [0, 42]) ----------------
__device__ __forceinline__ void threefry(uint32_t c0, uint32_t c1,
                                         uint32_t& o0, uint32_t& o1) {
  const uint32_t K0 = 0u, K1 = 42u, K2 = 0x1BD11BDAu ^ 0u ^ 42u;
  uint32_t x0 = c0 + K0, x1 = c1 + K1;
#define TFR(rr) { x0 += x1; x1 = __funnelshift_l(x1, x1, rr); x1 ^= x0; }
  TFR(13) TFR(15) TFR(26) TFR(6)   x0 += K1; x1 += K2 + 1u;
  TFR(17) TFR(29) TFR(16) TFR(24)  x0 += K2; x1 += K0 + 2u;
  TFR(13) TFR(15) TFR(26) TFR(6)   x0 += K0; x1 += K1 + 3u;
  TFR(17) TFR(29) TFR(16) TFR(24)  x0 += K1; x1 += K2 + 4u;
  TFR(13) TFR(15) TFR(26) TFR(6)   x0 += K2; x1 += K0 + 5u;
#undef TFR
  o0 = x0; o1 = x1;
}

__device__ __forceinline__ float bits_to_normal(uint32_t bits) {
  float f = __uint_as_float((bits >> 9) | 0x3F800000u) - 1.0f;
  float x = fmaxf(-0.99999994f, fmaf(f, 2.0f, -0.99999994f));
  float w = -__logf(fmaf(x, -x, 1.0f));
  float p;
  if (w < 5.0f) {
    w -= 2.5f;
    p = 2.81022636e-08f;
    p = fmaf(p, w, 3.43273939e-07f);
    p = fmaf(p, w, -3.5233877e-06f);
    p = fmaf(p, w, -4.39150654e-06f);
    p = fmaf(p, w, 0.00021858087f);
    p = fmaf(p, w, -0.00125372503f);
    p = fmaf(p, w, -0.00417768164f);
    p = fmaf(p, w, 0.246640727f);
    p = fmaf(p, w, 1.50140941f);
  } else {
    w = sqrtf(w) - 3.0f;
    p = -0.000200214257f;
    p = fmaf(p, w, 0.000100950558f);
    p = fmaf(p, w, 0.00134934322f);
    p = fmaf(p, w, -0.00367342844f);
    p = fmaf(p, w, 0.00573950773f);
    p = fmaf(p, w, -0.0076224613f);
    p = fmaf(p, w, 0.00943887047f);
    p = fmaf(p, w, 1.00167406f);
    p = fmaf(p, w, 2.83297682f);
  }
  return 1.4142135623730951f * (p * x);
}

// ---------------- K4: recompute-w combine + inline noise -> output ----------------
__global__ void __launch_bounds__(256) k_out(const float* __restrict__ wt,
                                             float* __restrict__ out) {
  __shared__ float scf[384];
  __shared__ float sC[32], sF[32], sK[4];
  int t = threadIdx.x;
  for (int i = t; i < 384; i += 256) scf[i] = g_acoef[i];
  if (t < 32) { sC[t] = g_Cc[t]; sF[t] = g_Ff[t]; }
  if (t < 4) sK[t] = g_Kk[t];
  __syncthreads();
  int q = blockIdx.x * 256 + t;            // float4 index (2 pixels)
  const float4* W4 = (const float4*)wt;
  float acc0[4], acc1[4];
#pragma unroll
  for (int b = 0; b < 4; b++) { acc0[b] = sK[b]; acc1[b] = sK[b]; }
#pragma unroll
  for (int r = 0; r < 8; r++) {
    float4 A0 = W4[(size_t)(4 * r + 0) * (NPIX / 2) + q];
    float4 A1 = W4[(size_t)(4 * r + 1) * (NPIX / 2) + q];
    float4 B0 = W4[(size_t)(4 * r + 2) * (NPIX / 2) + q];
    float4 B1 = W4[(size_t)(4 * r + 3) * (NPIX / 2) + q];
#pragma unroll
    for (int b = 0; b < 4; b++) {
      const float* c = &scf[(b * 8 + r) * 12];
      float w0 = wval(c, A0.x, A0.y, B0.x, B0.y, A1.x, A1.y, B1.x, B1.y);
      float w1 = wval(c, A0.z, A0.w, B0.z, B0.w, A1.z, A1.w, B1.z, B1.w);
      float Cr = sC[b * 8 + r];
      acc0[b] = fmaf(Cr, w0, acc0[b]);
      acc1[b] = fmaf(Cr, w1, acc1[b]);
    }
  }
  // inline noise: pixel n0 = 2q, n1 = 2q+1
#pragma unroll
  for (int px = 0; px < 2; px++) {
    uint32_t n = 2u * (uint32_t)q + (uint32_t)px;
#pragma unroll
    for (int j = 0; j < 16; j++) {          // j = b2*8 + r, b2 in {0,1}
      uint32_t idx = ((uint32_t)j << 18) | n;
      uint32_t o0, o1;
      threefry(idx, idx + HALFCNT, o0, o1);
      float n0 = bits_to_normal(o0);
      float n1 = bits_to_normal(o1);
      int b2 = j >> 3;
      if (px == 0) {
        acc0[b2]     = fmaf(sF[j],      n0, acc0[b2]);
        acc0[b2 + 2] = fmaf(sF[j + 16], n1, acc0[b2 + 2]);
      } else {
        acc1[b2]     = fmaf(sF[j],      n0, acc1[b2]);
        acc1[b2 + 2] = fmaf(sF[j + 16], n1, acc1[b2 + 2]);
      }
    }
  }
  float2* O2 = (float2*)out;
#pragma unroll
  for (int b = 0; b < 4; b++)
    O2[(size_t)b * (NPIX / 2) + q] = make_float2(acc0[b], acc1[b]);
}

extern "C" void kernel_launch(void* const* d_in, const int* in_sizes, int n_in,
                              void* d_out, int out_size) {
  const float* x  = (const float*)d_in[0];
  const float* cw = (const float*)d_in[1];
  const float* cb = (const float*)d_in[2];
  const float* wt = (const float*)d_in[3];
  float* out = (float*)d_out;
  const int dynsmem = (32 * 512 + 384) * sizeof(float);  // 67072 B
  cudaFuncSetAttribute(k_gramA, cudaFuncAttributeMaxDynamicSharedMemorySize, dynsmem);
  k_xt<<<210, 128>>>(x, cw, cb);
  k_mods<<<1, 128>>>();
  k_gramA<<<GBLK, 256, dynsmem>>>(wt);
  k_fin<<<1, 704>>>();
  k_out<<<NPIX / 512, 256>>>(wt, out);
}

// round 6
// speedup vs baseline: 1.0762x; 1.0762x over previous
#include <cuda_runtime.h>
#include <cuda_bf16.h>
#include <cstdint>

#define NPIX 262144               // 512*512 = 2^18
#define HALFCNT 4194304u          // 2^22 threefry counter half
#define GBLK 512                  // k_gramA blocks (512 px each)

// ---------------- device scratch (allocation-free) ----------------
__device__ float g_xt[4 * 210];
__device__ float g_acoef[4 * 8 * 2 * 6];  // [b][r][j][bb0,bb1,p,q,u,v] = 384 floats
__device__ float g_wr[4 * 8];             // softmaxed rank weights (first 8 of 9)
__device__ float g_part[4 * GBLK * 44];   // gram partials per (b, block)
__device__ float g_G[176];                // reduced gram/sums [b][44]
__device__ float g_Cc[4 * 8];             // combine coefs
__device__ float g_Ff[4 * 8];             // noise std coefs
__device__ float g_Kk[4];                 // mean shift

// ---------------- K0a: xt = x @ ctx_w^T + ctx_b ----------------
__global__ void k_xt(const float* __restrict__ x, const float* __restrict__ cw,
                     const float* __restrict__ cb) {
  int f = blockIdx.x;          // 0..209
  int t = threadIdx.x;         // 128
  const float* wrow = cw + f * 512;
  float a0 = 0.f, a1 = 0.f, a2 = 0.f, a3 = 0.f;
  for (int i = t; i < 512; i += 128) {
    float w = wrow[i];
    a0 = fmaf(w, x[i], a0);
    a1 = fmaf(w, x[512 + i], a1);
    a2 = fmaf(w, x[1024 + i], a2);
    a3 = fmaf(w, x[1536 + i], a3);
  }
#pragma unroll
  for (int o = 16; o; o >>= 1) {
    a0 += __shfl_xor_sync(~0u, a0, o);
    a1 += __shfl_xor_sync(~0u, a1, o);
    a2 += __shfl_xor_sync(~0u, a2, o);
    a3 += __shfl_xor_sync(~0u, a3, o);
  }
  __shared__ float sm[4][4];
  int wq = t >> 5, l = t & 31;
  if (l == 0) { sm[wq][0] = a0; sm[wq][1] = a1; sm[wq][2] = a2; sm[wq][3] = a3; }
  __syncthreads();
  if (t == 0) {
    float bb = cb[f];
#pragma unroll
    for (int b = 0; b < 4; b++)
      g_xt[b * 210 + f] = sm[0][b] + sm[1][b] + sm[2][b] + sm[3][b] + bb;
  }
}

// ---------------- K0b: gate, affine modulation coefs, wr softmax ----------------
__global__ void k_mods() {
  int t = threadIdx.x;  // 128
  __shared__ float gated[4][105];
  for (int i = t; i < 420; i += 128) {
    int b = i / 105, k = i - 105 * b;
    float a1 = g_xt[b * 210 + k], a2 = g_xt[b * 210 + 105 + k];
    gated[b][k] = a1 * tanhf(a2);
  }
  __syncthreads();
  if (t < 64) {
    int b = t >> 4, r = (t >> 1) & 7, j = t & 1;
    int base = r * 12 + j * 2;
    float c0 = gated[b][base + 0] + 0.5f;
    float c1 = gated[b][base + 1];
    float bb0 = gated[b][base + 4];
    float bb1 = gated[b][base + 5];
    float s0 = gated[b][base + 8] + 1.0f;
    float s1 = gated[b][base + 9];
    float omc = 1.0f - c0;
    float p = s0 * omc + s1 * c1;
    float q = s0 * c1 - s1 * omc;
    float u = s0 * c0 - s1 * c1;
    float v = -(s0 * c1 + s1 * c0);
    float* dst = &g_acoef[((b * 8 + r) * 2 + j) * 6];
    dst[0] = bb0; dst[1] = bb1; dst[2] = p; dst[3] = q; dst[4] = u; dst[5] = v;
  }
  if (t < 4) {
    int b = t;
    float w[9];
#pragma unroll
    for (int i = 0; i < 9; i++) w[i] = gated[b][96 + i];
    w[8] += 0.35355339059327373f;  // 1/sqrt(8)
    float ss = 0.f;
#pragma unroll
    for (int i = 0; i < 9; i++) ss += w[i] * w[i];
    float inv = 1.0f / fmaxf(sqrtf(ss), 1e-12f);
    float mx = -3.4e38f;
#pragma unroll
    for (int i = 0; i < 9; i++) { w[i] *= inv; mx = fmaxf(mx, w[i]); }
    float sum = 0.f;
#pragma unroll
    for (int i = 0; i < 9; i++) { w[i] = expf(w[i] - mx); sum += w[i]; }
    float isum = 1.0f / sum;
#pragma unroll
    for (int i = 0; i < 8; i++) g_wr[b * 8 + i] = w[i] * isum;
  }
}

// w for one (b,r,pixel) given the 12 affine coefs and the 2 complex weights
__device__ __forceinline__ float wval(const float* c, float are, float aim,
                                      float bre, float bim,
                                      float a1re, float a1im, float b1re, float b1im) {
  float nr = c[0] + c[2] * are + c[3] * aim + c[4] * bre + c[5] * bim;
  float ni = c[1] - c[3] * are + c[2] * aim - c[5] * bre + c[4] * bim;
  float er = c[6] + c[8] * a1re + c[9] * a1im + c[10] * b1re + c[11] * b1im;
  float ei = c[7] - c[9] * a1re + c[8] * a1im - c[11] * b1re + c[10] * b1im;
  float d2 = er * er + ei * ei;
  float inv = rsqrtf(fmaxf(d2, 1e-12f));
  return (nr * er + ni * ei) * inv;
}

// triangular pair index: s <= t
#define TIDX(s, t) ((s) * 8 - (s) * ((s)-1) / 2 + ((t) - (s)))

// ---------------- K1: fused w-compute + Gram (no DRAM scratch) ----------------
__global__ void __launch_bounds__(256) k_gramA(const float* __restrict__ wt) {
  extern __shared__ float dyn[];
  float* sw = dyn;                 // [(b*8+r)*512 + px]
  float* scf = dyn + 32 * 512;     // 384 coefs
  __shared__ float red[8][44];
  int t = threadIdx.x;
  for (int i = t; i < 384; i += 256) scf[i] = g_acoef[i];
  __syncthreads();
  // ---- phase 1: compute w for 2 pixels (float4 = 2 complex) ----
  int q = blockIdx.x * 256 + t;             // float4 index within plane
  const float4* W4 = (const float4*)wt;
#pragma unroll
  for (int r = 0; r < 8; r++) {
    float4 A0 = W4[(size_t)(4 * r + 0) * (NPIX / 2) + q];
    float4 A1 = W4[(size_t)(4 * r + 1) * (NPIX / 2) + q];
    float4 B0 = W4[(size_t)(4 * r + 2) * (NPIX / 2) + q];
    float4 B1 = W4[(size_t)(4 * r + 3) * (NPIX / 2) + q];
#pragma unroll
    for (int b = 0; b < 4; b++) {
      const float* c = &scf[(b * 8 + r) * 12];
      float w0 = wval(c, A0.x, A0.y, B0.x, B0.y, A1.x, A1.y, B1.x, B1.y);
      float w1 = wval(c, A0.z, A0.w, B0.z, B0.w, A1.z, A1.w, B1.z, B1.w);
      ((float2*)sw)[(b * 8 + r) * 256 + t] = make_float2(w0, w1);
    }
  }
  __syncthreads();
  // ---- phase 2: per-batch Gram + sums from smem ----
  int wq = t >> 5, lane = t & 31;
  int b = wq >> 1, half = wq & 1;
  float a[36], su[8];
#pragma unroll
  for (int k = 0; k < 36; k++) a[k] = 0.f;
#pragma unroll
  for (int k = 0; k < 8; k++) su[k] = 0.f;
#pragma unroll
  for (int k = 0; k < 8; k++) {
    int px = half * 256 + k * 32 + lane;
    float v[8];
#pragma unroll
    for (int s = 0; s < 8; s++) v[s] = sw[(b * 8 + s) * 512 + px];
#pragma unroll
    for (int s = 0; s < 8; s++) {
      su[s] += v[s];
#pragma unroll
      for (int u = s; u < 8; u++) a[TIDX(s, u)] = fmaf(v[s], v[u], a[TIDX(s, u)]);
    }
  }
#pragma unroll
  for (int k = 0; k < 36; k++)
#pragma unroll
    for (int o = 16; o; o >>= 1) a[k] += __shfl_xor_sync(~0u, a[k], o);
#pragma unroll
  for (int k = 0; k < 8; k++)
#pragma unroll
    for (int o = 16; o; o >>= 1) su[k] += __shfl_xor_sync(~0u, su[k], o);
  if (lane == 0) {
#pragma unroll
    for (int k = 0; k < 36; k++) red[wq][k] = a[k];
#pragma unroll
    for (int k = 0; k < 8; k++) red[wq][36 + k] = su[k];
  }
  __syncthreads();
  if (t < 176) {
    int bb = t / 44, j = t - 44 * bb;
    g_part[(bb * GBLK + blockIdx.x) * 44 + j] = red[2 * bb][j] + red[2 * bb + 1][j];
  }
}

// ---------------- K2: reduce partials: 176 blocks, one (b,j) each ----------------
__global__ void __launch_bounds__(256) k_red() {
  int bid = blockIdx.x;            // 0..175
  int b = bid / 44, j = bid - 44 * b;
  int t = threadIdx.x;             // 256
  float acc = g_part[(size_t)(b * GBLK + t) * 44 + j] +
              g_part[(size_t)(b * GBLK + t + 256) * 44 + j];
#pragma unroll
  for (int o = 16; o; o >>= 1) acc += __shfl_xor_sync(~0u, acc, o);
  __shared__ float s[8];
  if ((t & 31) == 0) s[t >> 5] = acc;
  __syncthreads();
  if (t == 0) {
    float r = 0.f;
#pragma unroll
    for (int k = 0; k < 8; k++) r += s[k];
    g_G[bid] = r;
  }
}

// ---------------- K3: finalize coefficients (tiny) ----------------
__global__ void k_fin() {
  int t = threadIdx.x;  // 32
  if (t < 4) {
    int b = t;
    const float* sG = &g_G[b * 44];
    float G[8][8], S[8];
#pragma unroll
    for (int s = 0; s < 8; s++)
#pragma unroll
      for (int u = s; u < 8; u++) { float g = sG[TIDX(s, u)]; G[s][u] = g; G[u][s] = g; }
#pragma unroll
    for (int s = 0; s < 8; s++) S[s] = sG[36 + s];
    float nc[8];
#pragma unroll
    for (int s = 0; s < 8; s++) nc[s] = fmaxf(sqrtf(G[s][s]), 1e-12f);
    float Gh[8][8];
#pragma unroll
    for (int s = 0; s < 8; s++)
#pragma unroll
      for (int u = 0; u < 8; u++) Gh[s][u] = G[s][u] / (nc[s] * nc[u]);
    const float alpha = 0.1f / (7.0f * 2.8284271247461903f);  // 0.1/(7*sqrt(8))
    float A[8][8];
#pragma unroll
    for (int s = 0; s < 8; s++)
#pragma unroll
      for (int u = 0; u < 8; u++) A[s][u] = (s == u) ? 1.0f : -alpha * Gh[s][u];
    float C[8], K = 0.f;
#pragma unroll
    for (int s = 0; s < 8; s++) C[s] = 0.f;
#pragma unroll
    for (int r = 0; r < 8; r++) {
      float q = 0.f;
#pragma unroll
      for (int u = 0; u < 8; u++) {
        float v = 0.f;
#pragma unroll
        for (int s = 0; s < 8; s++) v += A[r][s] * Gh[s][u];
        q += v * A[r][u];
      }
      float mc = fmaxf(sqrtf(fmaxf(q, 0.f)), 1e-12f);
      double meand = 0.0;
      float wr = g_wr[b * 8 + r];
#pragma unroll
      for (int s = 0; s < 8; s++) {
        float D = A[r][s] / (nc[s] * mc);
        C[s] += wr * D;
        meand += (double)D * (double)S[s];
      }
      meand /= (double)NPIX;
      double var = (1.0 - (double)NPIX * meand * meand) / (double)(NPIX - 1);
      if (var < 0.0) var = 0.0;
      double stdd = sqrt(var);
      if (stdd < 1e-12) stdd = 1e-12;
      g_Ff[b * 8 + r] = 0.01f * wr * (float)stdd;
      K += 0.01f * wr * (float)meand;
    }
#pragma unroll
    for (int s = 0; s < 8; s++) g_Cc[b * 8 + s] = C[s];
    g_Kk[b] = K;
  }
}

// ---------------- threefry2x32 (JAX, key = [0, 42]) ----------------
__device__ __forceinline__ void threefry(uint32_t c0, uint32_t c1,
                                         uint32_t& o0, uint32_t& o1) {
  const uint32_t K0 = 0u, K1 = 42u, K2 = 0x1BD11BDAu ^ 0u ^ 42u;
  uint32_t x0 = c0 + K0, x1 = c1 + K1;
#define TFR(rr) { x0 += x1; x1 = __funnelshift_l(x1, x1, rr); x1 ^= x0; }
  TFR(13) TFR(15) TFR(26) TFR(6)   x0 += K1; x1 += K2 + 1u;
  TFR(17) TFR(29) TFR(16) TFR(24)  x0 += K2; x1 += K0 + 2u;
  TFR(13) TFR(15) TFR(26) TFR(6)   x0 += K0; x1 += K1 + 3u;
  TFR(17) TFR(29) TFR(16) TFR(24)  x0 += K1; x1 += K2 + 4u;
  TFR(13) TFR(15) TFR(26) TFR(6)   x0 += K2; x1 += K0 + 5u;
#undef TFR
  o0 = x0; o1 = x1;
}

__device__ __forceinline__ float bits_to_normal(uint32_t bits) {
  float f = __uint_as_float((bits >> 9) | 0x3F800000u) - 1.0f;
  float x = fmaxf(-0.99999994f, fmaf(f, 2.0f, -0.99999994f));
  float w = -__logf(fmaf(x, -x, 1.0f));
  float p;
  if (w < 5.0f) {
    w -= 2.5f;
    p = 2.81022636e-08f;
    p = fmaf(p, w, 3.43273939e-07f);
    p = fmaf(p, w, -3.5233877e-06f);
    p = fmaf(p, w, -4.39150654e-06f);
    p = fmaf(p, w, 0.00021858087f);
    p = fmaf(p, w, -0.00125372503f);
    p = fmaf(p, w, -0.00417768164f);
    p = fmaf(p, w, 0.246640727f);
    p = fmaf(p, w, 1.50140941f);
  } else {
    w = sqrtf(w) - 3.0f;
    p = -0.000200214257f;
    p = fmaf(p, w, 0.000100950558f);
    p = fmaf(p, w, 0.00134934322f);
    p = fmaf(p, w, -0.00367342844f);
    p = fmaf(p, w, 0.00573950773f);
    p = fmaf(p, w, -0.0076224613f);
    p = fmaf(p, w, 0.00943887047f);
    p = fmaf(p, w, 1.00167406f);
    p = fmaf(p, w, 2.83297682f);
  }
  return 1.4142135623730951f * (p * x);
}

// ---------------- K4: recompute-w combine + inline noise -> output ----------------
__global__ void __launch_bounds__(256) k_out(const float* __restrict__ wt,
                                             float* __restrict__ out) {
  __shared__ float scf[384];
  __shared__ float sC[32], sF[32], sK[4];
  int t = threadIdx.x;
  for (int i = t; i < 384; i += 256) scf[i] = g_acoef[i];
  if (t < 32) { sC[t] = g_Cc[t]; sF[t] = g_Ff[t]; }
  if (t < 4) sK[t] = g_Kk[t];
  __syncthreads();
  int q = blockIdx.x * 256 + t;            // float4 index (2 pixels)
  const float4* W4 = (const float4*)wt;
  float acc0[4], acc1[4];
#pragma unroll
  for (int b = 0; b < 4; b++) { acc0[b] = sK[b]; acc1[b] = sK[b]; }
#pragma unroll
  for (int r = 0; r < 8; r++) {
    float4 A0 = W4[(size_t)(4 * r + 0) * (NPIX / 2) + q];
    float4 A1 = W4[(size_t)(4 * r + 1) * (NPIX / 2) + q];
    float4 B0 = W4[(size_t)(4 * r + 2) * (NPIX / 2) + q];
    float4 B1 = W4[(size_t)(4 * r + 3) * (NPIX / 2) + q];
#pragma unroll
    for (int b = 0; b < 4; b++) {
      const float* c = &scf[(b * 8 + r) * 12];
      float w0 = wval(c, A0.x, A0.y, B0.x, B0.y, A1.x, A1.y, B1.x, B1.y);
      float w1 = wval(c, A0.z, A0.w, B0.z, B0.w, A1.z, A1.w, B1.z, B1.w);
      float Cr = sC[b * 8 + r];
      acc0[b] = fmaf(Cr, w0, acc0[b]);
      acc1[b] = fmaf(Cr, w1, acc1[b]);
    }
  }
  // inline noise: pixel n0 = 2q, n1 = 2q+1
#pragma unroll
  for (int px = 0; px < 2; px++) {
    uint32_t n = 2u * (uint32_t)q + (uint32_t)px;
#pragma unroll
    for (int j = 0; j < 16; j++) {          // j = b2*8 + r, b2 in {0,1}
      uint32_t idx = ((uint32_t)j << 18) | n;
      uint32_t o0, o1;
      threefry(idx, idx + HALFCNT, o0, o1);
      float n0 = bits_to_normal(o0);
      float n1 = bits_to_normal(o1);
      int b2 = j >> 3;
      if (px == 0) {
        acc0[b2]     = fmaf(sF[j],      n0, acc0[b2]);
        acc0[b2 + 2] = fmaf(sF[j + 16], n1, acc0[b2 + 2]);
      } else {
        acc1[b2]     = fmaf(sF[j],      n0, acc1[b2]);
        acc1[b2 + 2] = fmaf(sF[j + 16], n1, acc1[b2 + 2]);
      }
    }
  }
  float2* O2 = (float2*)out;
#pragma unroll
  for (int b = 0; b < 4; b++)
    O2[(size_t)b * (NPIX / 2) + q] = make_float2(acc0[b], acc1[b]);
}

extern "C" void kernel_launch(void* const* d_in, const int* in_sizes, int n_in,
                              void* d_out, int out_size) {
  const float* x  = (const float*)d_in[0];
  const float* cw = (const float*)d_in[1];
  const float* cb = (const float*)d_in[2];
  const float* wt = (const float*)d_in[3];
  float* out = (float*)d_out;
  const int dynsmem = (32 * 512 + 384) * sizeof(float);  // 67072 B
  cudaFuncSetAttribute(k_gramA, cudaFuncAttributeMaxDynamicSharedMemorySize, dynsmem);
  k_xt<<<210, 128>>>(x, cw, cb);
  k_mods<<<1, 128>>>();
  k_gramA<<<GBLK, 256, dynsmem>>>(wt);
  k_red<<<176, 256>>>();
  k_fin<<<1, 32>>>();
  k_out<<<NPIX / 512, 256>>>(wt, out);
}